// round 4
// baseline (speedup 1.0000x reference)
#include <cuda_runtime.h>
#include <cuda_bf16.h>

// RelaxedProd: B=32, N=128, D=4096, shared_errors = 128 = N1 = N2.
// s == N1 == N2 collapses all zero-padding and the moveaxis transposes
// cancel, so everything is elementwise / n-reduced in native (B,N,D) layout:
//   out_lin[b,n,d] = ch*ce2 + ch2*ce1
//   prod_sum[b,d]  = sum_n ce1*ce2
//   abs_prod[b,d]  = sum_n |ce1*ce2|
//   abs_sum[b,d]   = sum_n |ce1|
//   new_head       = ch*ch2 + 0.5*prod_sum
//   qe             = abs_sum^2 - 0.5*abs_prod
//   out_adv[b,n,d] = qe * adv
//
// R4 design: float4 (LDG.128/STG.128) everywhere, NO block barriers.
// Warp layout: 8 consecutive float4 columns x 4 n-chunks of 32 rows
// (lane = col(0..7) + 8*chunk). Reductions combined with shfl.xor(8,16).
// Streaming cache hints (__ldcs/__stcs) since every byte is touched once.
// 512 blocks x 256 threads (131072 threads = 32768 fl4-cols x 4 chunks).

#define RP_B 32
#define RP_N 128
#define RP_D 4096
#define RP_D4 (RP_D / 4)      // 1024 float4 per row
#define NPC 32                // rows per n-chunk (128 / 4)

__device__ __forceinline__ float4 ldcs4(const float4* p) {
    return __ldcs(p);
}

__global__ __launch_bounds__(256, 3)
void relaxed_prod_kernel(const float4* __restrict__ ch,
                         const float4* __restrict__ ce1,
                         const float4* __restrict__ ch2,
                         const float4* __restrict__ ce2,
                         const float4* __restrict__ adv,
                         float4* __restrict__ out_head,
                         float4* __restrict__ out_err) {
    const int T      = blockIdx.x * blockDim.x + threadIdx.x;  // 0 .. 131071
    const int lane   = threadIdx.x & 31;
    const int chunk  = lane >> 3;                 // n-chunk 0..3
    const int wglob  = T >> 5;                    // global warp id 0..4095
    const int c      = wglob * 8 + (lane & 7);    // float4 column 0..32767
    const int b      = c >> 10;                   // c / RP_D4
    const int dcol   = c & (RP_D4 - 1);
    const int n0     = chunk * NPC;

    const long long ibase = ((long long)b * RP_N + n0) * RP_D4 + dcol;
    const long long obase = ((long long)b * 2 * RP_N + n0) * RP_D4 + dcol;

    const float4 h1 = ch[c];
    const float4 h2 = ch2[c];

    float4 ps = make_float4(0.f, 0.f, 0.f, 0.f);
    float4 ap = make_float4(0.f, 0.f, 0.f, 0.f);
    float4 as = make_float4(0.f, 0.f, 0.f, 0.f);

    // Pass 1: lin-err output + three partial reductions; batch 8 LDG.128.
    #pragma unroll 2
    for (int j = 0; j < NPC; j += 4) {
        float4 a[4], e[4];
        const long long off = ibase + (long long)j * RP_D4;
        #pragma unroll
        for (int i = 0; i < 4; ++i) {
            a[i] = ldcs4(ce1 + off + (long long)i * RP_D4);
            e[i] = ldcs4(ce2 + off + (long long)i * RP_D4);
        }
        const long long ooff = obase + (long long)j * RP_D4;
        #pragma unroll
        for (int i = 0; i < 4; ++i) {
            float4 o;
            o.x = h1.x * e[i].x + h2.x * a[i].x;
            o.y = h1.y * e[i].y + h2.y * a[i].y;
            o.z = h1.z * e[i].z + h2.z * a[i].z;
            o.w = h1.w * e[i].w + h2.w * a[i].w;
            __stcs(out_err + ooff + (long long)i * RP_D4, o);
            const float px = a[i].x * e[i].x, py = a[i].y * e[i].y;
            const float pz = a[i].z * e[i].z, pw = a[i].w * e[i].w;
            ps.x += px;        ps.y += py;        ps.z += pz;        ps.w += pw;
            ap.x += fabsf(px); ap.y += fabsf(py); ap.z += fabsf(pz); ap.w += fabsf(pw);
            as.x += fabsf(a[i].x); as.y += fabsf(a[i].y);
            as.z += fabsf(a[i].z); as.w += fabsf(a[i].w);
        }
    }

    // Combine the 4 n-chunk partials across lanes (same column = lane xor 8,16).
    #pragma unroll
    for (int m = 8; m <= 16; m <<= 1) {
        ps.x += __shfl_xor_sync(0xffffffffu, ps.x, m);
        ps.y += __shfl_xor_sync(0xffffffffu, ps.y, m);
        ps.z += __shfl_xor_sync(0xffffffffu, ps.z, m);
        ps.w += __shfl_xor_sync(0xffffffffu, ps.w, m);
        ap.x += __shfl_xor_sync(0xffffffffu, ap.x, m);
        ap.y += __shfl_xor_sync(0xffffffffu, ap.y, m);
        ap.z += __shfl_xor_sync(0xffffffffu, ap.z, m);
        ap.w += __shfl_xor_sync(0xffffffffu, ap.w, m);
        as.x += __shfl_xor_sync(0xffffffffu, as.x, m);
        as.y += __shfl_xor_sync(0xffffffffu, as.y, m);
        as.z += __shfl_xor_sync(0xffffffffu, as.z, m);
        as.w += __shfl_xor_sync(0xffffffffu, as.w, m);
    }

    if (chunk == 0) {
        float4 hd;
        hd.x = h1.x * h2.x + 0.5f * ps.x;
        hd.y = h1.y * h2.y + 0.5f * ps.y;
        hd.z = h1.z * h2.z + 0.5f * ps.z;
        hd.w = h1.w * h2.w + 0.5f * ps.w;
        out_head[c] = hd;
    }

    float4 qe;
    qe.x = as.x * as.x - 0.5f * ap.x;
    qe.y = as.y * as.y - 0.5f * ap.y;
    qe.z = as.z * as.z - 0.5f * ap.z;
    qe.w = as.w * as.w - 0.5f * ap.w;

    // Pass 2: stream adv scaled by qe into the second half of new_errors.
    const long long obase2 = obase + (long long)RP_N * RP_D4;
    #pragma unroll 2
    for (int j = 0; j < NPC; j += 4) {
        float4 v[4];
        const long long off = ibase + (long long)j * RP_D4;
        #pragma unroll
        for (int i = 0; i < 4; ++i)
            v[i] = ldcs4(adv + off + (long long)i * RP_D4);
        const long long ooff = obase2 + (long long)j * RP_D4;
        #pragma unroll
        for (int i = 0; i < 4; ++i) {
            float4 o;
            o.x = qe.x * v[i].x;
            o.y = qe.y * v[i].y;
            o.z = qe.z * v[i].z;
            o.w = qe.w * v[i].w;
            __stcs(out_err + ooff + (long long)i * RP_D4, o);
        }
    }
}

extern "C" void kernel_launch(void* const* d_in, const int* in_sizes, int n_in,
                              void* d_out, int out_size) {
    const float4* ch  = (const float4*)d_in[0];   // curr_head     (B, D)
    const float4* ce1 = (const float4*)d_in[1];   // curr_errors   (B, N, D)
    const float4* ch2 = (const float4*)d_in[2];   // curr_head_2   (B, D)
    const float4* ce2 = (const float4*)d_in[3];   // curr_errors_2 (B, N, D)
    const float4* adv = (const float4*)d_in[4];   // adv_errors    (B, N, D)
    // d_in[5] = shared_errors (== N; padding collapses — unused at runtime)

    float4* out_head = (float4*)d_out;                          // B*D floats
    float4* out_err  = (float4*)((float*)d_out + RP_B * RP_D);  // B*2N*D floats

    const int threads = 256;
    const int blocks  = (RP_B * RP_D4 * 4) / threads;  // 512
    relaxed_prod_kernel<<<blocks, threads>>>(ch, ce1, ch2, ce2, adv,
                                             out_head, out_err);
}

// round 5
// speedup vs baseline: 1.0010x; 1.0010x over previous
#include <cuda_runtime.h>
#include <cuda_bf16.h>

// RelaxedProd: B=32, N=128, D=4096, shared_errors = 128 = N1 = N2.
// s == N1 == N2 collapses all zero-padding and the moveaxis transposes
// cancel, so everything is elementwise / n-reduced in native (B,N,D) layout:
//   out_lin[b,n,d] = ch*ce2 + ch2*ce1
//   prod_sum[b,d]  = sum_n ce1*ce2
//   abs_prod[b,d]  = sum_n |ce1*ce2|
//   abs_sum[b,d]   = sum_n |ce1|
//   new_head       = ch*ch2 + 0.5*prod_sum
//   qe             = abs_sum^2 - 0.5*abs_prod
//   out_adv[b,n,d] = qe * adv
//
// R5 = R3 (best bench: 59.9us) with ONE change: bulk stores use __stwt
// (write-through) instead of __stcs. Rationale: four structurally different
// kernels all plateau at ~60-68% DRAM; the remaining limiter is dirty-L2
// writeback interleaving with demand reads + post-kernel flush bleeding into
// the next graph replay. Write-through removes all dirty L2 state.

#define RP_B 32
#define RP_N 128
#define RP_D 4096
#define UNR 8

__global__ __launch_bounds__(256, 4)
void relaxed_prod_kernel(const float* __restrict__ ch,
                         const float* __restrict__ ce1,
                         const float* __restrict__ ch2,
                         const float* __restrict__ ce2,
                         const float* __restrict__ adv,
                         float* __restrict__ out_head,
                         float* __restrict__ out_err) {
    const int t = blockIdx.x * blockDim.x + threadIdx.x;   // 0 .. B*D-1
    const int b = t >> 12;          // t / D
    const int d = t & (RP_D - 1);   // t % D

    const long long base  = (long long)b * RP_N * RP_D + d;
    const long long obase = (long long)b * 2 * RP_N * RP_D + d;

    const float h1 = ch[t];
    const float h2 = ch2[t];

    float prod_sum = 0.0f;
    float abs_prod = 0.0f;
    float abs_sum  = 0.0f;

    // Pass 1: lin-err output + three reductions, 16 loads batched per chunk.
    #pragma unroll 2
    for (int n0 = 0; n0 < RP_N; n0 += UNR) {
        float a[UNR], e[UNR];
        const long long off = base + (long long)n0 * RP_D;
        #pragma unroll
        for (int i = 0; i < UNR; ++i) {
            a[i] = __ldcs(ce1 + off + (long long)i * RP_D);
            e[i] = __ldcs(ce2 + off + (long long)i * RP_D);
        }
        const long long ooff = obase + (long long)n0 * RP_D;
        #pragma unroll
        for (int i = 0; i < UNR; ++i) {
            __stwt(out_err + ooff + (long long)i * RP_D, h1 * e[i] + h2 * a[i]);
            const float p = a[i] * e[i];
            prod_sum += p;
            abs_prod += fabsf(p);
            abs_sum  += fabsf(a[i]);
        }
    }

    out_head[t] = h1 * h2 + 0.5f * prod_sum;
    const float qe = abs_sum * abs_sum - 0.5f * abs_prod;

    // Pass 2: stream adv scaled by qe into the second half of new_errors.
    const long long obase2 = obase + (long long)RP_N * RP_D;
    #pragma unroll 2
    for (int n0 = 0; n0 < RP_N; n0 += UNR) {
        float v[UNR];
        const long long off = base + (long long)n0 * RP_D;
        #pragma unroll
        for (int i = 0; i < UNR; ++i)
            v[i] = __ldcs(adv + off + (long long)i * RP_D);
        const long long ooff = obase2 + (long long)n0 * RP_D;
        #pragma unroll
        for (int i = 0; i < UNR; ++i)
            __stwt(out_err + ooff + (long long)i * RP_D, qe * v[i]);
    }
}

extern "C" void kernel_launch(void* const* d_in, const int* in_sizes, int n_in,
                              void* d_out, int out_size) {
    const float* ch  = (const float*)d_in[0];   // curr_head     (B, D)
    const float* ce1 = (const float*)d_in[1];   // curr_errors   (B, N, D)
    const float* ch2 = (const float*)d_in[2];   // curr_head_2   (B, D)
    const float* ce2 = (const float*)d_in[3];   // curr_errors_2 (B, N, D)
    const float* adv = (const float*)d_in[4];   // adv_errors    (B, N, D)
    // d_in[5] = shared_errors (== N; padding collapses — unused at runtime)

    float* out_head = (float*)d_out;                 // B*D elements
    float* out_err  = (float*)d_out + RP_B * RP_D;   // B*2N*D elements

    const int total   = RP_B * RP_D;     // 131072 columns
    const int threads = 256;
    const int blocks  = total / threads; // 512
    relaxed_prod_kernel<<<blocks, threads>>>(ch, ce1, ch2, ce2, adv,
                                             out_head, out_err);
}

// round 6
// speedup vs baseline: 1.0569x; 1.0559x over previous
#include <cuda_runtime.h>
#include <cuda_bf16.h>

// RelaxedProd: B=32, N=128, D=4096, shared_errors = 128 = N1 = N2.
// s == N1 == N2 collapses all zero-padding and the moveaxis transposes
// cancel, so everything is elementwise / n-reduced in native (B,N,D) layout:
//   out_lin[b,n,d] = ch*ce2 + ch2*ce1
//   prod_sum[b,d]  = sum_n ce1*ce2
//   abs_prod[b,d]  = sum_n |ce1*ce2|
//   abs_sum[b,d]   = sum_n |ce1|
//   new_head       = ch*ch2 + 0.5*prod_sum
//   qe             = abs_sum^2 - 0.5*abs_prod
//   out_adv[b,n,d] = qe * adv
//
// R6 = R3 body (best bench 59.9us: scalar columns, 16-load batches, __ldcs
// loads, __stcs stores) with ONE change: 128-thread blocks x 1024 blocks
// instead of 256 x 512. 512 blocks over 152 SMs put 4 resident blocks on 56
// SMs and 3 on 96 (19% per-SM work skew); 1024 blocks cut the skew to 4%
// with identical per-thread code. stwt reverted (R5 regressed the bench).

#define RP_B 32
#define RP_N 128
#define RP_D 4096
#define UNR 8

__global__ __launch_bounds__(128, 8)
void relaxed_prod_kernel(const float* __restrict__ ch,
                         const float* __restrict__ ce1,
                         const float* __restrict__ ch2,
                         const float* __restrict__ ce2,
                         const float* __restrict__ adv,
                         float* __restrict__ out_head,
                         float* __restrict__ out_err) {
    const int t = blockIdx.x * blockDim.x + threadIdx.x;   // 0 .. B*D-1
    const int b = t >> 12;          // t / D
    const int d = t & (RP_D - 1);   // t % D

    const long long base  = (long long)b * RP_N * RP_D + d;
    const long long obase = (long long)b * 2 * RP_N * RP_D + d;

    const float h1 = ch[t];
    const float h2 = ch2[t];

    float prod_sum = 0.0f;
    float abs_prod = 0.0f;
    float abs_sum  = 0.0f;

    // Pass 1: lin-err output + three reductions, 16 loads batched per chunk.
    #pragma unroll 2
    for (int n0 = 0; n0 < RP_N; n0 += UNR) {
        float a[UNR], e[UNR];
        const long long off = base + (long long)n0 * RP_D;
        #pragma unroll
        for (int i = 0; i < UNR; ++i) {
            a[i] = __ldcs(ce1 + off + (long long)i * RP_D);
            e[i] = __ldcs(ce2 + off + (long long)i * RP_D);
        }
        const long long ooff = obase + (long long)n0 * RP_D;
        #pragma unroll
        for (int i = 0; i < UNR; ++i) {
            __stcs(out_err + ooff + (long long)i * RP_D, h1 * e[i] + h2 * a[i]);
            const float p = a[i] * e[i];
            prod_sum += p;
            abs_prod += fabsf(p);
            abs_sum  += fabsf(a[i]);
        }
    }

    out_head[t] = h1 * h2 + 0.5f * prod_sum;
    const float qe = abs_sum * abs_sum - 0.5f * abs_prod;

    // Pass 2: stream adv scaled by qe into the second half of new_errors.
    const long long obase2 = obase + (long long)RP_N * RP_D;
    #pragma unroll 2
    for (int n0 = 0; n0 < RP_N; n0 += UNR) {
        float v[UNR];
        const long long off = base + (long long)n0 * RP_D;
        #pragma unroll
        for (int i = 0; i < UNR; ++i)
            v[i] = __ldcs(adv + off + (long long)i * RP_D);
        const long long ooff = obase2 + (long long)n0 * RP_D;
        #pragma unroll
        for (int i = 0; i < UNR; ++i)
            __stcs(out_err + ooff + (long long)i * RP_D, qe * v[i]);
    }
}

extern "C" void kernel_launch(void* const* d_in, const int* in_sizes, int n_in,
                              void* d_out, int out_size) {
    const float* ch  = (const float*)d_in[0];   // curr_head     (B, D)
    const float* ce1 = (const float*)d_in[1];   // curr_errors   (B, N, D)
    const float* ch2 = (const float*)d_in[2];   // curr_head_2   (B, D)
    const float* ce2 = (const float*)d_in[3];   // curr_errors_2 (B, N, D)
    const float* adv = (const float*)d_in[4];   // adv_errors    (B, N, D)
    // d_in[5] = shared_errors (== N; padding collapses — unused at runtime)

    float* out_head = (float*)d_out;                 // B*D elements
    float* out_err  = (float*)d_out + RP_B * RP_D;   // B*2N*D elements

    const int total   = RP_B * RP_D;      // 131072 columns
    const int threads = 128;
    const int blocks  = total / threads;  // 1024
    relaxed_prod_kernel<<<blocks, threads>>>(ch, ce1, ch2, ce2, adv,
                                             out_head, out_err);
}